// round 4
// baseline (speedup 1.0000x reference)
#include <cuda_runtime.h>

#define BB 1024
#define TT 256
#define HH 256
#define OUTD 9
#define PL 16
#define INPAD 272   // 9 + 256 = 265, padded to 272

typedef unsigned long long u64;

// ---------------- device scratch ----------------
__device__ __align__(16) float g_reprs[BB * TT * 3];
__device__ __align__(16) float g_enc[(size_t)BB * TT * HH];
__device__ __align__(16) float g_eproj[(size_t)BB * TT * HH];
__device__ __align__(16) float g_h[2][BB * HH];
__device__ __align__(16) float g_hd[2][BB * HH];
__device__ __align__(16) float g_dproj[BB * HH];
__device__ __align__(16) float g_inp[BB * INPAD];
__device__ __align__(16) float g_wihp[768 * INPAD];
__device__ __align__(16) float g_wtd[HH * HH];
__device__ __align__(16) float g_wte[HH * HH];
__device__ unsigned g_barcnt[8];

// ---------------- math helpers ----------------
__device__ __forceinline__ float ex2f(float x) {
    float r; asm("ex2.approx.f32 %0, %1;" : "=f"(r) : "f"(x)); return r;
}
__device__ __forceinline__ float frcp(float x) {
    float r; asm("rcp.approx.f32 %0, %1;" : "=f"(r) : "f"(x)); return r;
}
__device__ __forceinline__ float sigf(float x) {
    return frcp(1.0f + ex2f(-1.4426950408889634f * x));
}
__device__ __forceinline__ float tanhf_fast(float x) {
    float ax = fabsf(x);
    float e = ex2f(-2.8853900817779268f * ax);
    float r = (1.0f - e) * frcp(1.0f + e);
    return copysignf(r, x);
}
__device__ __forceinline__ u64 pack2(float lo, float hi) {
    u64 r;
    asm("mov.b64 %0, {%1, %2};" : "=l"(r)
        : "r"(__float_as_uint(lo)), "r"(__float_as_uint(hi)));
    return r;
}
__device__ __forceinline__ void unpack2(u64 v, float& lo, float& hi) {
    unsigned a, b;
    asm("mov.b64 {%0, %1}, %2;" : "=r"(a), "=r"(b) : "l"(v));
    lo = __uint_as_float(a); hi = __uint_as_float(b);
}
__device__ __forceinline__ void fma2(u64& d, u64 a, u64 b) {
    asm("fma.rn.f32x2 %0, %1, %2, %0;" : "+l"(d) : "l"(a), "l"(b));
}
__device__ __forceinline__ float warp_sum(float v) {
#pragma unroll
    for (int o = 16; o > 0; o >>= 1) v += __shfl_xor_sync(0xffffffffu, v, o);
    return v;
}
__device__ __forceinline__ unsigned ld_acq(const unsigned* p) {
    unsigned v;
    asm volatile("ld.acquire.gpu.u32 %0, [%1];" : "=r"(v) : "l"(p));
    return v;
}

// ---------------- init ----------------
__global__ void init_kernel(const float* __restrict__ x,
                            const float* __restrict__ dWih,
                            const float* __restrict__ Wt) {
    int idx = blockIdx.x * blockDim.x + threadIdx.x;
    int stride = gridDim.x * blockDim.x;
    if (idx < 8) g_barcnt[idx] = 0u;
    for (int i = idx; i < BB * HH; i += stride) g_h[0][i] = 0.0f;
    for (int i = idx; i < 768 * INPAD; i += stride) {
        int row = i / INPAD, c = i - row * INPAD;
        g_wihp[i] = (c < OUTD + HH) ? dWih[row * (OUTD + HH) + c] : 0.0f;
    }
    for (int i = idx; i < HH * HH; i += stride) {
        int g = i >> 8, c = i & 255;
        g_wtd[i] = Wt[g * (2 * HH) + c];
        g_wte[i] = Wt[g * (2 * HH) + HH + c];
    }
    for (int i = idx; i < BB * INPAD; i += stride) {
        int b = i / INPAD, c = i - b * INPAD;
        g_inp[i] = (c < OUTD) ? x[((size_t)b * TT + (TT - 1)) * OUTD + c] : 0.0f;
    }
}

// ---------------- stage 1: agent attention ----------------
__global__ __launch_bounds__(256) void agent_attn_kernel(
        const float* __restrict__ x, const float* __restrict__ Wa,
        const float* __restrict__ ba, const float* __restrict__ va) {
    __shared__ float Was[HH * 3];
    __shared__ float vas[HH];
    __shared__ float bas[HH];
    int tid = threadIdx.x;
    for (int i = tid; i < HH * 3; i += 256) Was[i] = Wa[i];
    vas[tid] = va[tid];
    bas[tid] = ba[tid];
    __syncthreads();

    int pair = blockIdx.x * 8 + (tid >> 5);
    int lane = tid & 31;
    const float* xp = &x[(size_t)pair * 9];
    float xv[9];
#pragma unroll
    for (int i = 0; i < 9; i++) xv[i] = xp[i];

    float sc[3];
#pragma unroll
    for (int a = 0; a < 3; a++) {
        float s = 0.0f;
        float x0 = xv[a * 3], x1 = xv[a * 3 + 1], x2 = xv[a * 3 + 2];
#pragma unroll
        for (int i = 0; i < 8; i++) {
            int h = lane + 32 * i;
            float e = tanhf_fast(fmaf(x2, Was[h * 3 + 2],
                          fmaf(x1, Was[h * 3 + 1], x0 * Was[h * 3])) + bas[h]);
            s += e * vas[h];
        }
        sc[a] = warp_sum(s);
    }
    float m = fmaxf(sc[0], fmaxf(sc[1], sc[2]));
    float e0 = ex2f((sc[0] - m) * 1.4426950408889634f);
    float e1 = ex2f((sc[1] - m) * 1.4426950408889634f);
    float e2 = ex2f((sc[2] - m) * 1.4426950408889634f);
    float inv = frcp(e0 + e1 + e2);
    float a0 = e0 * inv, a1 = e1 * inv, a2 = e2 * inv;
    if (lane < 3) {
        g_reprs[pair * 3 + lane] =
            a0 * xv[lane] + a1 * xv[3 + lane] + a2 * xv[6 + lane];
    }
}

// ---------------- stage 2: persistent encoder (512 threads) ----------------
// 128 blocks = 16 batch-groups (64 rows) x 8 h-groups (32 h x 3 gates).
// Thread (tx 0..15, ty 0..31): 2 batch rows x 2 h cols x 3 gates.
#define ENC_SMEM (98304 + 66560 + (192 + 288 + 96 + 96) * 4)

__global__ __launch_bounds__(512) void enc_persistent(
        const float* __restrict__ Whh, const float* __restrict__ Wih,
        const float* __restrict__ bih, const float* __restrict__ bhh) {
    extern __shared__ __align__(16) char smraw[];
    u64* Wp = (u64*)smraw;                          // [3][128][32] u64
    u64* Ha = (u64*)(smraw + 98304);                // [128][65] u64 (padded)
    float* Xs   = (float*)(smraw + 98304 + 66560);  // [64][3]
    float* Wihs = Xs + 192;                         // [3*32][3]
    float* bihs = Wihs + 288;                       // [3][32]
    float* bhhs = bihs + 96;                        // [3][32]

    int tid = threadIdx.x;
    int bid = blockIdx.x;
    int bm0 = (bid >> 3) * 64;
    int hb0 = (bid & 7) * 32;
    int tx = tid & 15, ty = tid >> 4;   // ty 0..31

    // ---- one-time weight staging ----
    for (int i = tid; i < 3 * 32 * 128; i += 512) {
        int kp = i & 127, h = (i >> 7) & 31, g = i >> 12;
        float2 v = *(const float2*)&Whh[(size_t)(g * HH + hb0 + h) * HH + kp * 2];
        Wp[(g * 128 + kp) * 32 + h] = pack2(v.x, v.y);
    }
    for (int i = tid; i < 288; i += 512) {
        int g = i / 96, r = i % 96, h = r / 3, f = r % 3;
        Wihs[(g * 32 + h) * 3 + f] = Wih[(size_t)(g * HH + hb0 + h) * 3 + f];
    }
    if (tid < 96) {
        int g = tid >> 5, h = tid & 31;
        bihs[g * 32 + h] = bih[g * HH + hb0 + h];
        bhhs[g * 32 + h] = bhh[g * HH + hb0 + h];
    }
    __syncthreads();

    for (int t = 0; t < TT; t++) {
        // ---- stage h_{t-1} into Ha (k-pair packed, [kp][batch]) ----
        if (t == 0) {
            for (int i = tid; i < 128 * 65; i += 512) Ha[i] = 0ull;
        } else {
            for (int i = tid; i < 4096; i += 512) {
                int b = i >> 6, kq = i & 63;
                float4 v = __ldcv((const float4*)
                    &g_enc[((size_t)(bm0 + b) * TT + (t - 1)) * HH + kq * 4]);
                Ha[(2 * kq) * 65 + b]     = pack2(v.x, v.y);
                Ha[(2 * kq + 1) * 65 + b] = pack2(v.z, v.w);
            }
        }
        if (tid < 192) {
            int b = tid / 3, f = tid % 3;
            Xs[b * 3 + f] = g_reprs[((size_t)(bm0 + b) * TT + t) * 3 + f];
        }
        __syncthreads();

        // ---- GEMM: acc[g][i(2 batch)][j(2 h)] over 128 k-pairs ----
        u64 acc[3][2][2];
#pragma unroll
        for (int g = 0; g < 3; g++)
#pragma unroll
            for (int i = 0; i < 2; i++)
#pragma unroll
                for (int j = 0; j < 2; j++) acc[g][i][j] = 0ull;

        const u64* ha = &Ha[ty * 2];
        const u64* wp = &Wp[tx * 2];
#pragma unroll 4
        for (int kp = 0; kp < 128; kp++) {
            u64 a0 = ha[0], a1 = ha[1];
            ulonglong2 w0 = *(const ulonglong2*)&wp[0];
            ulonglong2 w1 = *(const ulonglong2*)&wp[128 * 32];
            ulonglong2 w2 = *(const ulonglong2*)&wp[256 * 32];
            fma2(acc[0][0][0], a0, w0.x); fma2(acc[0][0][1], a0, w0.y);
            fma2(acc[0][1][0], a1, w0.x); fma2(acc[0][1][1], a1, w0.y);
            fma2(acc[1][0][0], a0, w1.x); fma2(acc[1][0][1], a0, w1.y);
            fma2(acc[1][1][0], a1, w1.x); fma2(acc[1][1][1], a1, w1.y);
            fma2(acc[2][0][0], a0, w2.x); fma2(acc[2][0][1], a0, w2.y);
            fma2(acc[2][1][0], a1, w2.x); fma2(acc[2][1][1], a1, w2.y);
            ha += 65;
            wp += 32;
        }

        // ---- gate epilogue + write h_t ----
#pragma unroll
        for (int i = 0; i < 2; i++) {
            int bl = ty * 2 + i;
            int b = bm0 + bl;
            float x0 = Xs[bl * 3], x1 = Xs[bl * 3 + 1], x2 = Xs[bl * 3 + 2];
            float hn2[2];
#pragma unroll
            for (int j = 0; j < 2; j++) {
                int hl = tx * 2 + j;
                float lo, hi, ghr, ghz, ghn;
                unpack2(acc[0][i][j], lo, hi); ghr = lo + hi;
                unpack2(acc[1][i][j], lo, hi); ghz = lo + hi;
                unpack2(acc[2][i][j], lo, hi); ghn = lo + hi;
                const float* wr = &Wihs[(0 * 32 + hl) * 3];
                const float* wz = &Wihs[(1 * 32 + hl) * 3];
                const float* wn = &Wihs[(2 * 32 + hl) * 3];
                float gi_r = fmaf(x2, wr[2], fmaf(x1, wr[1], x0 * wr[0])) + bihs[0 * 32 + hl];
                float gi_z = fmaf(x2, wz[2], fmaf(x1, wz[1], x0 * wz[0])) + bihs[1 * 32 + hl];
                float gi_n = fmaf(x2, wn[2], fmaf(x1, wn[1], x0 * wn[0])) + bihs[2 * 32 + hl];
                float r = sigf(gi_r + ghr + bhhs[0 * 32 + hl]);
                float z = sigf(gi_z + ghz + bhhs[1 * 32 + hl]);
                float n = tanhf_fast(gi_n + r * (ghn + bhhs[2 * 32 + hl]));
                float plo, phi;
                unpack2(Ha[((hb0 >> 1) + tx) * 65 + bl], plo, phi);
                float hprev = (j == 0) ? plo : phi;
                hn2[j] = n + z * (hprev - n);
            }
            *(float2*)&g_enc[((size_t)b * TT + t) * HH + hb0 + tx * 2] =
                make_float2(hn2[0], hn2[1]);
            if (t == TT - 1) {
                *(float2*)&g_h[0][(size_t)b * HH + hb0 + tx * 2] =
                    make_float2(hn2[0], hn2[1]);
            }
        }

        // ---- grid barrier (8 counters, 16 arrivals each) ----
        __syncthreads();
        if (tid == 0) {
            __threadfence();
            atomicAdd(&g_barcnt[bid & 7], 1u);
        }
        if (tid < 8) {
            unsigned target = 16u * (unsigned)(t + 1);
            while (ld_acq(&g_barcnt[tid]) < target) { }
        }
        __syncthreads();
    }
}

// ---------------- shared GEMM-gate tile phase (decoder) ----------------
template <int TGN>
__device__ __forceinline__ void gemm_gate_phase(
        u64 (&acc)[4][4],
        const float* __restrict__ Ain, int astr,
        const float* __restrict__ Wm, int wstr, int Ktot,
        int bm0, int hb0, int tid, int tx, int ty,
        float (&As)[16][64], float (&Ws)[3][16][32]) {
    int lr = tid >> 2, lq = tid & 3;
    for (int k0 = 0; k0 < Ktot; k0 += 16) {
        __syncthreads();
        {
            float4 v = *(const float4*)&Ain[(size_t)(bm0 + lr) * astr + k0 + lq * 4];
            As[lq * 4 + 0][lr] = v.x; As[lq * 4 + 1][lr] = v.y;
            As[lq * 4 + 2][lr] = v.z; As[lq * 4 + 3][lr] = v.w;
        }
        for (int i = tid; i < 384; i += 256) {
            int row = i >> 2, q = i & 3, g = row >> 5, hh = row & 31;
            float4 v = *(const float4*)&Wm[(size_t)(g * HH + hb0 + hh) * wstr + k0 + q * 4];
            Ws[g][q * 4 + 0][hh] = v.x; Ws[g][q * 4 + 1][hh] = v.y;
            Ws[g][q * 4 + 2][hh] = v.z; Ws[g][q * 4 + 3][hh] = v.w;
        }
        __syncthreads();
#pragma unroll
        for (int k = 0; k < 16; k++) {
            float4 a4 = *(const float4*)&As[k][ty * 4];
            u64 w0 = *(const u64*)&Ws[0][k][tx * 2];
            u64 w1 = *(const u64*)&Ws[1][k][tx * 2];
            u64 w2 = *(const u64*)&Ws[2][k][tx * 2];
            u64 a;
            a = pack2(a4.x, a4.x); fma2(acc[0][0], a, w0); fma2(acc[1][0], a, w1); fma2(acc[TGN][0], a, w2);
            a = pack2(a4.y, a4.y); fma2(acc[0][1], a, w0); fma2(acc[1][1], a, w1); fma2(acc[TGN][1], a, w2);
            a = pack2(a4.z, a4.z); fma2(acc[0][2], a, w0); fma2(acc[1][2], a, w1); fma2(acc[TGN][2], a, w2);
            a = pack2(a4.w, a4.w); fma2(acc[0][3], a, w0); fma2(acc[1][3], a, w1); fma2(acc[TGN][3], a, w2);
        }
    }
}

// ---------------- eproj: C = A @ W^T (64x64 tiles) ----------------
__global__ __launch_bounds__(256) void eproj_kernel() {
    const float* __restrict__ A = g_enc;
    const float* __restrict__ W = g_wte;
    float* __restrict__ C = g_eproj;
    const int K = HH, N = HH;
    __shared__ __align__(16) float As[16][64];
    __shared__ __align__(16) float Ws[16][64];
    int tid = threadIdx.x;
    int m0 = blockIdx.x * 64, n0 = blockIdx.y * 64;
    int tx = tid & 15, ty = tid >> 4;
    u64 acc[4][2];
#pragma unroll
    for (int i = 0; i < 4; i++)
#pragma unroll
        for (int j = 0; j < 2; j++) acc[i][j] = 0ull;
    int lr = tid >> 2, lq = tid & 3;
    for (int k0 = 0; k0 < K; k0 += 16) {
        __syncthreads();
        {
            float4 v = *(const float4*)&A[(size_t)(m0 + lr) * K + k0 + lq * 4];
            As[lq * 4 + 0][lr] = v.x; As[lq * 4 + 1][lr] = v.y;
            As[lq * 4 + 2][lr] = v.z; As[lq * 4 + 3][lr] = v.w;
        }
        {
            float4 v = *(const float4*)&W[(size_t)(n0 + lr) * K + k0 + lq * 4];
            Ws[lq * 4 + 0][lr] = v.x; Ws[lq * 4 + 1][lr] = v.y;
            Ws[lq * 4 + 2][lr] = v.z; Ws[lq * 4 + 3][lr] = v.w;
        }
        __syncthreads();
#pragma unroll
        for (int k = 0; k < 16; k++) {
            float4 a4 = *(const float4*)&As[k][ty * 4];
            u64 w0 = *(const u64*)&Ws[k][tx * 4];
            u64 w1 = *(const u64*)&Ws[k][tx * 4 + 2];
            u64 a;
            a = pack2(a4.x, a4.x); fma2(acc[0][0], a, w0); fma2(acc[0][1], a, w1);
            a = pack2(a4.y, a4.y); fma2(acc[1][0], a, w0); fma2(acc[1][1], a, w1);
            a = pack2(a4.z, a4.z); fma2(acc[2][0], a, w0); fma2(acc[2][1], a, w1);
            a = pack2(a4.w, a4.w); fma2(acc[3][0], a, w0); fma2(acc[3][1], a, w1);
        }
    }
#pragma unroll
    for (int i = 0; i < 4; i++) {
        int m = m0 + ty * 4 + i;
#pragma unroll
        for (int j = 0; j < 2; j++) {
            float lo, hi; unpack2(acc[i][j], lo, hi);
            int n = n0 + tx * 4 + j * 2;
            C[(size_t)m * N + n] = lo;
            C[(size_t)m * N + n + 1] = hi;
        }
    }
}

// ---------------- dproj: h @ Wt_dec^T + bt (32x32 tiles) ----------------
__global__ __launch_bounds__(256) void dproj_kernel(const float* __restrict__ bt, int s) {
    const float* A = (s == 0) ? g_h[0] : g_hd[s & 1];
    __shared__ __align__(16) float As[32][32];
    __shared__ __align__(16) float Ws[32][32];
    int tid = threadIdx.x;
    int m0 = blockIdx.x * 32, n0 = blockIdx.y * 32;
    int tx = tid & 15, ty = tid >> 4;
    u64 acc[2] = {0ull, 0ull};
    int lr = tid >> 3, lq = tid & 7;
    for (int k0 = 0; k0 < HH; k0 += 32) {
        __syncthreads();
        {
            float4 v = *(const float4*)&A[(size_t)(m0 + lr) * HH + k0 + lq * 4];
            As[lq * 4 + 0][lr] = v.x; As[lq * 4 + 1][lr] = v.y;
            As[lq * 4 + 2][lr] = v.z; As[lq * 4 + 3][lr] = v.w;
        }
        {
            float4 v = *(const float4*)&g_wtd[(size_t)(n0 + lr) * HH + k0 + lq * 4];
            Ws[lq * 4 + 0][lr] = v.x; Ws[lq * 4 + 1][lr] = v.y;
            Ws[lq * 4 + 2][lr] = v.z; Ws[lq * 4 + 3][lr] = v.w;
        }
        __syncthreads();
#pragma unroll
        for (int k = 0; k < 32; k++) {
            float2 a2 = *(const float2*)&As[k][ty * 2];
            u64 w = *(const u64*)&Ws[k][tx * 2];
            fma2(acc[0], pack2(a2.x, a2.x), w);
            fma2(acc[1], pack2(a2.y, a2.y), w);
        }
    }
#pragma unroll
    for (int i = 0; i < 2; i++) {
        float lo, hi; unpack2(acc[i], lo, hi);
        int m = m0 + ty * 2 + i, n = n0 + tx * 2;
        g_dproj[(size_t)m * HH + n] = lo + bt[n];
        g_dproj[(size_t)m * HH + n + 1] = hi + bt[n + 1];
    }
}

// ---------------- fused decoder temporal attention ----------------
// one block per batch row: scores (tanh dot) -> softmax -> context
__global__ __launch_bounds__(256) void dec_attn_kernel(const float* __restrict__ vt) {
    int b = blockIdx.x, tid = threadIdx.x;
    __shared__ float dps[HH], vts[HH], sc[TT], red[256];
    dps[tid] = g_dproj[(size_t)b * HH + tid];
    vts[tid] = vt[tid];
    __syncthreads();

    int w = tid >> 5, lane = tid & 31;
    const float* ep = &g_eproj[(size_t)b * TT * HH];
#pragma unroll 1
    for (int tl = 0; tl < 32; tl++) {
        int t = tl * 8 + w;
        const float* row = ep + (size_t)t * HH;
        float s = 0.0f;
#pragma unroll
        for (int i = 0; i < 8; i++) {
            int h = lane + 32 * i;
            s += tanhf_fast(row[h] + dps[h]) * vts[h];
        }
        s = warp_sum(s);
        if (lane == 0) sc[t] = s;
    }
    __syncthreads();

    // softmax over 256 scores
    float v = sc[tid];
    red[tid] = v;
    __syncthreads();
    for (int o = 128; o > 0; o >>= 1) {
        if (tid < o) red[tid] = fmaxf(red[tid], red[tid + o]);
        __syncthreads();
    }
    float m = red[0];
    __syncthreads();
    float e = ex2f((v - m) * 1.4426950408889634f);
    red[tid] = e;
    __syncthreads();
    for (int o = 128; o > 0; o >>= 1) {
        if (tid < o) red[tid] += red[tid + o];
        __syncthreads();
    }
    float tw = e * frcp(red[0]);
    sc[tid] = tw;
    __syncthreads();

    // context: h = tid
    const float* base = &g_enc[(size_t)b * TT * HH + tid];
    float acc = 0.0f;
#pragma unroll 8
    for (int t = 0; t < TT; t++) acc += sc[t] * base[(size_t)t * HH];
    g_inp[b * INPAD + OUTD + tid] = acc;
}

// ---------------- decoder GRU step ----------------
__global__ __launch_bounds__(256) void dec_gru_kernel(
        const float* __restrict__ Whh, const float* __restrict__ bih,
        const float* __restrict__ bhh, int s) {
    const float* hin = (s == 0) ? g_h[0] : g_hd[s & 1];
    float* hout = g_hd[(s + 1) & 1];

    __shared__ __align__(16) float As[16][64];
    __shared__ __align__(16) float Ws[3][16][32];
    __shared__ float bihs[3][32], bhhs[3][32];

    int tid = threadIdx.x;
    int bm0 = blockIdx.x * 64, hb0 = blockIdx.y * 32;
    int tx = tid & 15, ty = tid >> 4;
    if (tid < 96) {
        int g = tid >> 5, hh = tid & 31;
        bihs[g][hh] = bih[g * HH + hb0 + hh];
        bhhs[g][hh] = bhh[g * HH + hb0 + hh];
    }

    u64 acc[4][4];
#pragma unroll
    for (int g = 0; g < 4; g++)
#pragma unroll
        for (int i = 0; i < 4; i++) acc[g][i] = 0ull;

    gemm_gate_phase<2>(acc, hin, HH, Whh, HH, HH, bm0, hb0, tid, tx, ty, As, Ws);
    gemm_gate_phase<3>(acc, g_inp, INPAD, g_wihp, INPAD, INPAD, bm0, hb0, tid, tx, ty, As, Ws);

#pragma unroll
    for (int i = 0; i < 4; i++) {
        int b = bm0 + ty * 4 + i;
        float2 hp = *(const float2*)&hin[(size_t)b * HH + hb0 + tx * 2];
        float a0[2], a1[2], a2[2], a3[2];
        unpack2(acc[0][i], a0[0], a0[1]);
        unpack2(acc[1][i], a1[0], a1[1]);
        unpack2(acc[2][i], a2[0], a2[1]);
        unpack2(acc[3][i], a3[0], a3[1]);
#pragma unroll
        for (int j = 0; j < 2; j++) {
            int hl = tx * 2 + j;
            float r = sigf(a0[j] + bihs[0][hl] + bhhs[0][hl]);
            float z = sigf(a1[j] + bihs[1][hl] + bhhs[1][hl]);
            float n = tanhf_fast((a3[j] + bihs[2][hl]) + r * (a2[j] + bhhs[2][hl]));
            float hprev = (j == 0) ? hp.x : hp.y;
            float hn = n + z * (hprev - n);
            hout[(size_t)b * HH + hb0 + hl] = hn;
        }
    }
}

// ---------------- prediction head ----------------
__global__ __launch_bounds__(288) void pred_kernel(
        const float* __restrict__ Wfc, const float* __restrict__ bfc,
        float* __restrict__ out, int s) {
    int b = blockIdx.x, tid = threadIdx.x;
    const float* h = &g_hd[(s + 1) & 1][(size_t)b * HH];
    __shared__ float hs[HH];
    if (tid < HH) hs[tid] = h[tid];
    __syncthreads();
    int w = tid >> 5, lane = tid & 31;
    float sacc = 0.0f;
#pragma unroll
    for (int i = 0; i < 8; i++) {
        int hh = lane + 32 * i;
        sacc += hs[hh] * Wfc[w * HH + hh];
    }
    sacc = warp_sum(sacc);
    if (lane == 0) {
        float p = sacc + bfc[w];
        out[((size_t)b * PL + s) * OUTD + w] = p;
        g_inp[b * INPAD + w] = p;
    }
}

// ---------------- host orchestration ----------------
extern "C" void kernel_launch(void* const* d_in, const int* in_sizes, int n_in,
                              void* d_out, int out_size) {
    const float* x    = (const float*)d_in[0];
    const float* Wa   = (const float*)d_in[1];
    const float* ba   = (const float*)d_in[2];
    const float* va   = (const float*)d_in[3];
    const float* eWih = (const float*)d_in[4];
    const float* eWhh = (const float*)d_in[5];
    const float* ebih = (const float*)d_in[6];
    const float* ebhh = (const float*)d_in[7];
    const float* dWih = (const float*)d_in[8];
    const float* dWhh = (const float*)d_in[9];
    const float* dbih = (const float*)d_in[10];
    const float* dbhh = (const float*)d_in[11];
    const float* Wt   = (const float*)d_in[12];
    const float* bt   = (const float*)d_in[13];
    const float* vt   = (const float*)d_in[14];
    const float* Wfc  = (const float*)d_in[15];
    const float* bfc  = (const float*)d_in[16];
    float* out = (float*)d_out;

    init_kernel<<<256, 256>>>(x, dWih, Wt);
    agent_attn_kernel<<<(BB * TT) / 8, 256>>>(x, Wa, ba, va);

    cudaFuncSetAttribute(enc_persistent,
                         cudaFuncAttributeMaxDynamicSharedMemorySize, ENC_SMEM);
    enc_persistent<<<128, 512, ENC_SMEM>>>(eWhh, eWih, ebih, ebhh);

    eproj_kernel<<<dim3((BB * TT) / 64, HH / 64), 256>>>();

    for (int s = 0; s < PL; s++) {
        dproj_kernel<<<dim3(BB / 32, HH / 32), 256>>>(bt, s);
        dec_attn_kernel<<<BB, 256>>>(vt);
        dec_gru_kernel<<<dim3(BB / 64, HH / 32), 256>>>(dWhh, dbih, dbhh, s);
        pred_kernel<<<BB, 288>>>(Wfc, bfc, out, s);
    }
}

// round 5
// speedup vs baseline: 1.8405x; 1.8405x over previous
#include <cuda_runtime.h>

#define BB 1024
#define TT 256
#define HH 256
#define OUTD 9
#define PL 16
#define INPAD 272   // 9 + 256 = 265, padded to 272

typedef unsigned long long u64;

// ---------------- device scratch ----------------
__device__ __align__(16) float g_reprs[BB * TT * 3];
__device__ __align__(16) float g_enc[(size_t)BB * TT * HH];
__device__ __align__(16) float g_eproj[(size_t)BB * TT * HH];
__device__ __align__(16) float g_h[2][BB * HH];
__device__ __align__(16) float g_hd[2][BB * HH];
__device__ __align__(16) float g_dproj[BB * HH];
__device__ __align__(16) float g_ts[BB * TT];
__device__ __align__(16) float g_tw[BB * TT];
__device__ __align__(16) float g_inp[BB * INPAD];
__device__ __align__(16) float g_wihp[768 * INPAD];
__device__ __align__(16) float g_wtd[HH * HH];
__device__ __align__(16) float g_wte[HH * HH];
__device__ unsigned g_barcnt[16];

// ---------------- math helpers ----------------
__device__ __forceinline__ float ex2f(float x) {
    float r; asm("ex2.approx.f32 %0, %1;" : "=f"(r) : "f"(x)); return r;
}
__device__ __forceinline__ float frcp(float x) {
    float r; asm("rcp.approx.f32 %0, %1;" : "=f"(r) : "f"(x)); return r;
}
__device__ __forceinline__ float sigf(float x) {
    return frcp(1.0f + ex2f(-1.4426950408889634f * x));
}
__device__ __forceinline__ float tanhf_fast(float x) {
    float ax = fabsf(x);
    float e = ex2f(-2.8853900817779268f * ax);
    float r = (1.0f - e) * frcp(1.0f + e);
    return copysignf(r, x);
}
__device__ __forceinline__ u64 pack2(float lo, float hi) {
    u64 r;
    asm("mov.b64 %0, {%1, %2};" : "=l"(r)
        : "r"(__float_as_uint(lo)), "r"(__float_as_uint(hi)));
    return r;
}
__device__ __forceinline__ void unpack2(u64 v, float& lo, float& hi) {
    unsigned a, b;
    asm("mov.b64 {%0, %1}, %2;" : "=r"(a), "=r"(b) : "l"(v));
    lo = __uint_as_float(a); hi = __uint_as_float(b);
}
__device__ __forceinline__ void fma2(u64& d, u64 a, u64 b) {
    asm("fma.rn.f32x2 %0, %1, %2, %0;" : "+l"(d) : "l"(a), "l"(b));
}
__device__ __forceinline__ float warp_sum(float v) {
#pragma unroll
    for (int o = 16; o > 0; o >>= 1) v += __shfl_xor_sync(0xffffffffu, v, o);
    return v;
}
__device__ __forceinline__ unsigned ld_acq(const unsigned* p) {
    unsigned v;
    asm volatile("ld.acquire.gpu.u32 %0, [%1];" : "=r"(v) : "l"(p));
    return v;
}

// ---------------- init (split in two so enc_persistent is launch #4) ----------------
__global__ void init_a_kernel(const float* __restrict__ x) {
    int idx = blockIdx.x * blockDim.x + threadIdx.x;
    int stride = gridDim.x * blockDim.x;
    if (idx < 16) g_barcnt[idx] = 0u;
    for (int i = idx; i < BB * HH; i += stride) g_h[0][i] = 0.0f;
    for (int i = idx; i < BB * INPAD; i += stride) {
        int b = i / INPAD, c = i - b * INPAD;
        g_inp[i] = (c < OUTD) ? x[((size_t)b * TT + (TT - 1)) * OUTD + c] : 0.0f;
    }
}
__global__ void init_b_kernel(const float* __restrict__ dWih,
                              const float* __restrict__ Wt) {
    int idx = blockIdx.x * blockDim.x + threadIdx.x;
    int stride = gridDim.x * blockDim.x;
    for (int i = idx; i < 768 * INPAD; i += stride) {
        int row = i / INPAD, c = i - row * INPAD;
        g_wihp[i] = (c < OUTD + HH) ? dWih[row * (OUTD + HH) + c] : 0.0f;
    }
    for (int i = idx; i < HH * HH; i += stride) {
        int g = i >> 8, c = i & 255;
        g_wtd[i] = Wt[g * (2 * HH) + c];
        g_wte[i] = Wt[g * (2 * HH) + HH + c];
    }
}

// ---------------- stage 1: agent attention ----------------
__global__ __launch_bounds__(256) void agent_attn_kernel(
        const float* __restrict__ x, const float* __restrict__ Wa,
        const float* __restrict__ ba, const float* __restrict__ va) {
    __shared__ float Was[HH * 3];
    __shared__ float vas[HH];
    __shared__ float bas[HH];
    int tid = threadIdx.x;
    for (int i = tid; i < HH * 3; i += 256) Was[i] = Wa[i];
    vas[tid] = va[tid];
    bas[tid] = ba[tid];
    __syncthreads();

    int pair = blockIdx.x * 8 + (tid >> 5);
    int lane = tid & 31;
    const float* xp = &x[(size_t)pair * 9];
    float xv[9];
#pragma unroll
    for (int i = 0; i < 9; i++) xv[i] = xp[i];

    float sc[3];
#pragma unroll
    for (int a = 0; a < 3; a++) {
        float s = 0.0f;
        float x0 = xv[a * 3], x1 = xv[a * 3 + 1], x2 = xv[a * 3 + 2];
#pragma unroll
        for (int i = 0; i < 8; i++) {
            int h = lane + 32 * i;
            float e = tanhf_fast(fmaf(x2, Was[h * 3 + 2],
                          fmaf(x1, Was[h * 3 + 1], x0 * Was[h * 3])) + bas[h]);
            s += e * vas[h];
        }
        sc[a] = warp_sum(s);
    }
    float m = fmaxf(sc[0], fmaxf(sc[1], sc[2]));
    float e0 = ex2f((sc[0] - m) * 1.4426950408889634f);
    float e1 = ex2f((sc[1] - m) * 1.4426950408889634f);
    float e2 = ex2f((sc[2] - m) * 1.4426950408889634f);
    float inv = frcp(e0 + e1 + e2);
    float a0 = e0 * inv, a1 = e1 * inv, a2 = e2 * inv;
    if (lane < 3) {
        g_reprs[pair * 3 + lane] =
            a0 * xv[lane] + a1 * xv[3 + lane] + a2 * xv[6 + lane];
    }
}

// ---------------- stage 2: persistent encoder (256 threads, R3 config) ----------------
// 128 blocks = 16 batch-groups (64 rows) x 8 h-groups (32 h x 3 gates).
// h-exchange only couples the 8 h-blocks of one batch group -> per-group barrier.
#define ENC_SMEM (98304 + 66560 + (192 + 288 + 96 + 96) * 4)

__global__ __launch_bounds__(256) void enc_persistent(
        const float* __restrict__ Whh, const float* __restrict__ Wih,
        const float* __restrict__ bih, const float* __restrict__ bhh) {
    extern __shared__ __align__(16) char smraw[];
    u64* Wp = (u64*)smraw;                          // [3][128][32] u64
    u64* Ha = (u64*)(smraw + 98304);                // [128][65] u64 (padded)
    float* Xs   = (float*)(smraw + 98304 + 66560);  // [64][3]
    float* Wihs = Xs + 192;                         // [3*32][3]
    float* bihs = Wihs + 288;                       // [3][32]
    float* bhhs = bihs + 96;                        // [3][32]

    int tid = threadIdx.x;
    int bid = blockIdx.x;
    int bg  = bid >> 3;            // batch group 0..15
    int bm0 = bg * 64;
    int hb0 = (bid & 7) * 32;
    int tx = tid & 15, ty = tid >> 4;   // ty 0..15

    // ---- one-time weight staging ----
    for (int i = tid; i < 3 * 32 * 128; i += 256) {
        int kp = i & 127, h = (i >> 7) & 31, g = i >> 12;
        float2 v = *(const float2*)&Whh[(size_t)(g * HH + hb0 + h) * HH + kp * 2];
        Wp[(g * 128 + kp) * 32 + h] = pack2(v.x, v.y);
    }
    for (int i = tid; i < 288; i += 256) {
        int g = i / 96, r = i % 96, h = r / 3, f = r % 3;
        Wihs[(g * 32 + h) * 3 + f] = Wih[(size_t)(g * HH + hb0 + h) * 3 + f];
    }
    if (tid < 96) {
        int g = tid >> 5, h = tid & 31;
        bihs[g * 32 + h] = bih[g * HH + hb0 + h];
        bhhs[g * 32 + h] = bhh[g * HH + hb0 + h];
    }
    __syncthreads();

    for (int t = 0; t < TT; t++) {
        // ---- stage h_{t-1} into Ha (k-pair packed, [kp][batch]) ----
        if (t == 0) {
            for (int i = tid; i < 128 * 65; i += 256) Ha[i] = 0ull;
        } else {
            for (int i = tid; i < 4096; i += 256) {
                int b = i >> 6, kq = i & 63;
                float4 v = __ldcv((const float4*)
                    &g_enc[((size_t)(bm0 + b) * TT + (t - 1)) * HH + kq * 4]);
                Ha[(2 * kq) * 65 + b]     = pack2(v.x, v.y);
                Ha[(2 * kq + 1) * 65 + b] = pack2(v.z, v.w);
            }
        }
        if (tid < 192) {
            int b = tid / 3, f = tid % 3;
            Xs[b * 3 + f] = g_reprs[((size_t)(bm0 + b) * TT + t) * 3 + f];
        }
        __syncthreads();

        // ---- GEMM: acc[g][i(4 batch)][j(2 h)] over 128 k-pairs ----
        u64 acc[3][4][2];
#pragma unroll
        for (int g = 0; g < 3; g++)
#pragma unroll
            for (int i = 0; i < 4; i++)
#pragma unroll
                for (int j = 0; j < 2; j++) acc[g][i][j] = 0ull;

        const u64* ha = &Ha[ty * 4];
        const u64* wp = &Wp[tx * 2];
#pragma unroll 8
        for (int kp = 0; kp < 128; kp++) {
            u64 a0 = ha[0], a1 = ha[1], a2 = ha[2], a3 = ha[3];
            ulonglong2 w0 = *(const ulonglong2*)&wp[0];
            ulonglong2 w1 = *(const ulonglong2*)&wp[128 * 32];
            ulonglong2 w2 = *(const ulonglong2*)&wp[256 * 32];
            fma2(acc[0][0][0], a0, w0.x); fma2(acc[0][0][1], a0, w0.y);
            fma2(acc[0][1][0], a1, w0.x); fma2(acc[0][1][1], a1, w0.y);
            fma2(acc[0][2][0], a2, w0.x); fma2(acc[0][2][1], a2, w0.y);
            fma2(acc[0][3][0], a3, w0.x); fma2(acc[0][3][1], a3, w0.y);
            fma2(acc[1][0][0], a0, w1.x); fma2(acc[1][0][1], a0, w1.y);
            fma2(acc[1][1][0], a1, w1.x); fma2(acc[1][1][1], a1, w1.y);
            fma2(acc[1][2][0], a2, w1.x); fma2(acc[1][2][1], a2, w1.y);
            fma2(acc[1][3][0], a3, w1.x); fma2(acc[1][3][1], a3, w1.y);
            fma2(acc[2][0][0], a0, w2.x); fma2(acc[2][0][1], a0, w2.y);
            fma2(acc[2][1][0], a1, w2.x); fma2(acc[2][1][1], a1, w2.y);
            fma2(acc[2][2][0], a2, w2.x); fma2(acc[2][2][1], a2, w2.y);
            fma2(acc[2][3][0], a3, w2.x); fma2(acc[2][3][1], a3, w2.y);
            ha += 65;
            wp += 32;
        }

        // ---- gate epilogue + write h_t ----
#pragma unroll
        for (int i = 0; i < 4; i++) {
            int bl = ty * 4 + i;
            int b = bm0 + bl;
            float x0 = Xs[bl * 3], x1 = Xs[bl * 3 + 1], x2 = Xs[bl * 3 + 2];
            float hn2[2];
#pragma unroll
            for (int j = 0; j < 2; j++) {
                int hl = tx * 2 + j;
                float lo, hi, ghr, ghz, ghn;
                unpack2(acc[0][i][j], lo, hi); ghr = lo + hi;
                unpack2(acc[1][i][j], lo, hi); ghz = lo + hi;
                unpack2(acc[2][i][j], lo, hi); ghn = lo + hi;
                const float* wr = &Wihs[(0 * 32 + hl) * 3];
                const float* wz = &Wihs[(1 * 32 + hl) * 3];
                const float* wn = &Wihs[(2 * 32 + hl) * 3];
                float gi_r = fmaf(x2, wr[2], fmaf(x1, wr[1], x0 * wr[0])) + bihs[0 * 32 + hl];
                float gi_z = fmaf(x2, wz[2], fmaf(x1, wz[1], x0 * wz[0])) + bihs[1 * 32 + hl];
                float gi_n = fmaf(x2, wn[2], fmaf(x1, wn[1], x0 * wn[0])) + bihs[2 * 32 + hl];
                float r = sigf(gi_r + ghr + bhhs[0 * 32 + hl]);
                float z = sigf(gi_z + ghz + bhhs[1 * 32 + hl]);
                float n = tanhf_fast(gi_n + r * (ghn + bhhs[2 * 32 + hl]));
                float plo, phi;
                unpack2(Ha[((hb0 >> 1) + tx) * 65 + bl], plo, phi);
                float hprev = (j == 0) ? plo : phi;
                hn2[j] = n + z * (hprev - n);
            }
            *(float2*)&g_enc[((size_t)b * TT + t) * HH + hb0 + tx * 2] =
                make_float2(hn2[0], hn2[1]);
            if (t == TT - 1) {
                *(float2*)&g_h[0][(size_t)b * HH + hb0 + tx * 2] =
                    make_float2(hn2[0], hn2[1]);
            }
        }

        // ---- per-batch-group barrier (8 arrivals per counter) ----
        __syncthreads();
        if (tid == 0) {
            __threadfence();
            atomicAdd(&g_barcnt[bg], 1u);
        }
        if (tid == 0) {
            unsigned target = 8u * (unsigned)(t + 1);
            while (ld_acq(&g_barcnt[bg]) < target) { }
        }
        __syncthreads();
    }
}

// ---------------- shared GEMM-gate tile phase (decoder) ----------------
template <int TGN>
__device__ __forceinline__ void gemm_gate_phase(
        u64 (&acc)[4][4],
        const float* __restrict__ Ain, int astr,
        const float* __restrict__ Wm, int wstr, int Ktot,
        int bm0, int hb0, int tid, int tx, int ty,
        float (&As)[16][64], float (&Ws)[3][16][32]) {
    int lr = tid >> 2, lq = tid & 3;
    for (int k0 = 0; k0 < Ktot; k0 += 16) {
        __syncthreads();
        {
            float4 v = *(const float4*)&Ain[(size_t)(bm0 + lr) * astr + k0 + lq * 4];
            As[lq * 4 + 0][lr] = v.x; As[lq * 4 + 1][lr] = v.y;
            As[lq * 4 + 2][lr] = v.z; As[lq * 4 + 3][lr] = v.w;
        }
        for (int i = tid; i < 384; i += 256) {
            int row = i >> 2, q = i & 3, g = row >> 5, hh = row & 31;
            float4 v = *(const float4*)&Wm[(size_t)(g * HH + hb0 + hh) * wstr + k0 + q * 4];
            Ws[g][q * 4 + 0][hh] = v.x; Ws[g][q * 4 + 1][hh] = v.y;
            Ws[g][q * 4 + 2][hh] = v.z; Ws[g][q * 4 + 3][hh] = v.w;
        }
        __syncthreads();
#pragma unroll
        for (int k = 0; k < 16; k++) {
            float4 a4 = *(const float4*)&As[k][ty * 4];
            u64 w0 = *(const u64*)&Ws[0][k][tx * 2];
            u64 w1 = *(const u64*)&Ws[1][k][tx * 2];
            u64 w2 = *(const u64*)&Ws[2][k][tx * 2];
            u64 a;
            a = pack2(a4.x, a4.x); fma2(acc[0][0], a, w0); fma2(acc[1][0], a, w1); fma2(acc[TGN][0], a, w2);
            a = pack2(a4.y, a4.y); fma2(acc[0][1], a, w0); fma2(acc[1][1], a, w1); fma2(acc[TGN][1], a, w2);
            a = pack2(a4.z, a4.z); fma2(acc[0][2], a, w0); fma2(acc[1][2], a, w1); fma2(acc[TGN][2], a, w2);
            a = pack2(a4.w, a4.w); fma2(acc[0][3], a, w0); fma2(acc[1][3], a, w1); fma2(acc[TGN][3], a, w2);
        }
    }
}

// ---------------- eproj: C = A @ W^T (64x64 tiles) ----------------
__global__ __launch_bounds__(256) void eproj_kernel() {
    const float* __restrict__ A = g_enc;
    const float* __restrict__ W = g_wte;
    float* __restrict__ C = g_eproj;
    const int K = HH, N = HH;
    __shared__ __align__(16) float As[16][64];
    __shared__ __align__(16) float Ws[16][64];
    int tid = threadIdx.x;
    int m0 = blockIdx.x * 64, n0 = blockIdx.y * 64;
    int tx = tid & 15, ty = tid >> 4;
    u64 acc[4][2];
#pragma unroll
    for (int i = 0; i < 4; i++)
#pragma unroll
        for (int j = 0; j < 2; j++) acc[i][j] = 0ull;
    int lr = tid >> 2, lq = tid & 3;
    for (int k0 = 0; k0 < K; k0 += 16) {
        __syncthreads();
        {
            float4 v = *(const float4*)&A[(size_t)(m0 + lr) * K + k0 + lq * 4];
            As[lq * 4 + 0][lr] = v.x; As[lq * 4 + 1][lr] = v.y;
            As[lq * 4 + 2][lr] = v.z; As[lq * 4 + 3][lr] = v.w;
        }
        {
            float4 v = *(const float4*)&W[(size_t)(n0 + lr) * K + k0 + lq * 4];
            Ws[lq * 4 + 0][lr] = v.x; Ws[lq * 4 + 1][lr] = v.y;
            Ws[lq * 4 + 2][lr] = v.z; Ws[lq * 4 + 3][lr] = v.w;
        }
        __syncthreads();
#pragma unroll
        for (int k = 0; k < 16; k++) {
            float4 a4 = *(const float4*)&As[k][ty * 4];
            u64 w0 = *(const u64*)&Ws[k][tx * 4];
            u64 w1 = *(const u64*)&Ws[k][tx * 4 + 2];
            u64 a;
            a = pack2(a4.x, a4.x); fma2(acc[0][0], a, w0); fma2(acc[0][1], a, w1);
            a = pack2(a4.y, a4.y); fma2(acc[1][0], a, w0); fma2(acc[1][1], a, w1);
            a = pack2(a4.z, a4.z); fma2(acc[2][0], a, w0); fma2(acc[2][1], a, w1);
            a = pack2(a4.w, a4.w); fma2(acc[3][0], a, w0); fma2(acc[3][1], a, w1);
        }
    }
#pragma unroll
    for (int i = 0; i < 4; i++) {
        int m = m0 + ty * 4 + i;
#pragma unroll
        for (int j = 0; j < 2; j++) {
            float lo, hi; unpack2(acc[i][j], lo, hi);
            int n = n0 + tx * 4 + j * 2;
            C[(size_t)m * N + n] = lo;
            C[(size_t)m * N + n + 1] = hi;
        }
    }
}

// ---------------- dproj: h @ Wt_dec^T + bt (32x32 tiles) ----------------
__global__ __launch_bounds__(256) void dproj_kernel(const float* __restrict__ bt, int s) {
    const float* A = (s == 0) ? g_h[0] : g_hd[s & 1];
    __shared__ __align__(16) float As[32][32];
    __shared__ __align__(16) float Ws[32][32];
    int tid = threadIdx.x;
    int m0 = blockIdx.x * 32, n0 = blockIdx.y * 32;
    int tx = tid & 15, ty = tid >> 4;
    u64 acc[2] = {0ull, 0ull};
    int lr = tid >> 3, lq = tid & 7;
    for (int k0 = 0; k0 < HH; k0 += 32) {
        __syncthreads();
        {
            float4 v = *(const float4*)&A[(size_t)(m0 + lr) * HH + k0 + lq * 4];
            As[lq * 4 + 0][lr] = v.x; As[lq * 4 + 1][lr] = v.y;
            As[lq * 4 + 2][lr] = v.z; As[lq * 4 + 3][lr] = v.w;
        }
        {
            float4 v = *(const float4*)&g_wtd[(size_t)(n0 + lr) * HH + k0 + lq * 4];
            Ws[lq * 4 + 0][lr] = v.x; Ws[lq * 4 + 1][lr] = v.y;
            Ws[lq * 4 + 2][lr] = v.z; Ws[lq * 4 + 3][lr] = v.w;
        }
        __syncthreads();
#pragma unroll
        for (int k = 0; k < 32; k++) {
            float2 a2 = *(const float2*)&As[k][ty * 2];
            u64 w = *(const u64*)&Ws[k][tx * 2];
            fma2(acc[0], pack2(a2.x, a2.x), w);
            fma2(acc[1], pack2(a2.y, a2.y), w);
        }
    }
#pragma unroll
    for (int i = 0; i < 2; i++) {
        float lo, hi; unpack2(acc[i], lo, hi);
        int m = m0 + ty * 2 + i, n = n0 + tx * 2;
        g_dproj[(size_t)m * HH + n] = lo + bt[n];
        g_dproj[(size_t)m * HH + n + 1] = hi + bt[n + 1];
    }
}

// ---------------- decoder temporal attention (R3 layout) ----------------
__global__ __launch_bounds__(256) void tscore_kernel(const float* __restrict__ vt) {
    int b = blockIdx.y;
    int tid = threadIdx.x;
    __shared__ float dps[HH], vts[HH];
    dps[tid] = g_dproj[(size_t)b * HH + tid];
    vts[tid] = vt[tid];
    __syncthreads();
    int w = tid >> 5, lane = tid & 31;
    int t = blockIdx.x * 8 + w;
    const float* row = &g_eproj[((size_t)b * TT + t) * HH];
    float s = 0.0f;
#pragma unroll
    for (int i = 0; i < 8; i++) {
        int h = lane + 32 * i;
        s += tanhf_fast(row[h] + dps[h]) * vts[h];
    }
    s = warp_sum(s);
    if (lane == 0) g_ts[(size_t)b * TT + t] = s;
}

__global__ __launch_bounds__(256) void softmax_t_kernel() {
    int b = blockIdx.x, tid = threadIdx.x;
    __shared__ float sm[256];
    float v = g_ts[(size_t)b * TT + tid];
    sm[tid] = v;
    __syncthreads();
    for (int o = 128; o > 0; o >>= 1) {
        if (tid < o) sm[tid] = fmaxf(sm[tid], sm[tid + o]);
        __syncthreads();
    }
    float m = sm[0];
    __syncthreads();
    float e = ex2f((v - m) * 1.4426950408889634f);
    sm[tid] = e;
    __syncthreads();
    for (int o = 128; o > 0; o >>= 1) {
        if (tid < o) sm[tid] += sm[tid + o];
        __syncthreads();
    }
    g_tw[(size_t)b * TT + tid] = e * frcp(sm[0]);
}

__global__ __launch_bounds__(128) void context_kernel() {
    int b = blockIdx.y, tid = threadIdx.x;
    int h = blockIdx.x * 128 + tid;
    __shared__ float tws[TT];
    tws[tid] = g_tw[(size_t)b * TT + tid];
    tws[tid + 128] = g_tw[(size_t)b * TT + tid + 128];
    __syncthreads();
    const float* base = &g_enc[(size_t)b * TT * HH + h];
    float acc = 0.0f;
#pragma unroll 4
    for (int t = 0; t < TT; t++) acc += tws[t] * base[(size_t)t * HH];
    g_inp[b * INPAD + OUTD + h] = acc;
}

// ---------------- decoder GRU step ----------------
__global__ __launch_bounds__(256) void dec_gru_kernel(
        const float* __restrict__ Whh, const float* __restrict__ bih,
        const float* __restrict__ bhh, int s) {
    const float* hin = (s == 0) ? g_h[0] : g_hd[s & 1];
    float* hout = g_hd[(s + 1) & 1];

    __shared__ __align__(16) float As[16][64];
    __shared__ __align__(16) float Ws[3][16][32];
    __shared__ float bihs[3][32], bhhs[3][32];

    int tid = threadIdx.x;
    int bm0 = blockIdx.x * 64, hb0 = blockIdx.y * 32;
    int tx = tid & 15, ty = tid >> 4;
    if (tid < 96) {
        int g = tid >> 5, hh = tid & 31;
        bihs[g][hh] = bih[g * HH + hb0 + hh];
        bhhs[g][hh] = bhh[g * HH + hb0 + hh];
    }

    u64 acc[4][4];
#pragma unroll
    for (int g = 0; g < 4; g++)
#pragma unroll
        for (int i = 0; i < 4; i++) acc[g][i] = 0ull;

    gemm_gate_phase<2>(acc, hin, HH, Whh, HH, HH, bm0, hb0, tid, tx, ty, As, Ws);
    gemm_gate_phase<3>(acc, g_inp, INPAD, g_wihp, INPAD, INPAD, bm0, hb0, tid, tx, ty, As, Ws);

#pragma unroll
    for (int i = 0; i < 4; i++) {
        int b = bm0 + ty * 4 + i;
        float2 hp = *(const float2*)&hin[(size_t)b * HH + hb0 + tx * 2];
        float a0[2], a1[2], a2[2], a3[2];
        unpack2(acc[0][i], a0[0], a0[1]);
        unpack2(acc[1][i], a1[0], a1[1]);
        unpack2(acc[2][i], a2[0], a2[1]);
        unpack2(acc[3][i], a3[0], a3[1]);
#pragma unroll
        for (int j = 0; j < 2; j++) {
            int hl = tx * 2 + j;
            float r = sigf(a0[j] + bihs[0][hl] + bhhs[0][hl]);
            float z = sigf(a1[j] + bihs[1][hl] + bhhs[1][hl]);
            float n = tanhf_fast((a3[j] + bihs[2][hl]) + r * (a2[j] + bhhs[2][hl]));
            float hprev = (j == 0) ? hp.x : hp.y;
            float hn = n + z * (hprev - n);
            hout[(size_t)b * HH + hb0 + hl] = hn;
        }
    }
}

// ---------------- prediction head ----------------
__global__ __launch_bounds__(288) void pred_kernel(
        const float* __restrict__ Wfc, const float* __restrict__ bfc,
        float* __restrict__ out, int s) {
    int b = blockIdx.x, tid = threadIdx.x;
    const float* h = &g_hd[(s + 1) & 1][(size_t)b * HH];
    __shared__ float hs[HH];
    if (tid < HH) hs[tid] = h[tid];
    __syncthreads();
    int w = tid >> 5, lane = tid & 31;
    float sacc = 0.0f;
#pragma unroll
    for (int i = 0; i < 8; i++) {
        int hh = lane + 32 * i;
        sacc += hs[hh] * Wfc[w * HH + hh];
    }
    sacc = warp_sum(sacc);
    if (lane == 0) {
        float p = sacc + bfc[w];
        out[((size_t)b * PL + s) * OUTD + w] = p;
        g_inp[b * INPAD + w] = p;
    }
}

// ---------------- host orchestration ----------------
extern "C" void kernel_launch(void* const* d_in, const int* in_sizes, int n_in,
                              void* d_out, int out_size) {
    const float* x    = (const float*)d_in[0];
    const float* Wa   = (const float*)d_in[1];
    const float* ba   = (const float*)d_in[2];
    const float* va   = (const float*)d_in[3];
    const float* eWih = (const float*)d_in[4];
    const float* eWhh = (const float*)d_in[5];
    const float* ebih = (const float*)d_in[6];
    const float* ebhh = (const float*)d_in[7];
    const float* dWih = (const float*)d_in[8];
    const float* dWhh = (const float*)d_in[9];
    const float* dbih = (const float*)d_in[10];
    const float* dbhh = (const float*)d_in[11];
    const float* Wt   = (const float*)d_in[12];
    const float* bt   = (const float*)d_in[13];
    const float* vt   = (const float*)d_in[14];
    const float* Wfc  = (const float*)d_in[15];
    const float* bfc  = (const float*)d_in[16];
    float* out = (float*)d_out;

    // launch #1..#3, so enc_persistent is launch #4 (profiled position)
    init_a_kernel<<<256, 256>>>(x);
    init_b_kernel<<<256, 256>>>(dWih, Wt);
    agent_attn_kernel<<<(BB * TT) / 8, 256>>>(x, Wa, ba, va);

    cudaFuncSetAttribute(enc_persistent,
                         cudaFuncAttributeMaxDynamicSharedMemorySize, ENC_SMEM);
    enc_persistent<<<128, 256, ENC_SMEM>>>(eWhh, eWih, ebih, ebhh);

    eproj_kernel<<<dim3((BB * TT) / 64, HH / 64), 256>>>();

    for (int s = 0; s < PL; s++) {
        dproj_kernel<<<dim3(BB / 32, HH / 32), 256>>>(bt, s);
        tscore_kernel<<<dim3(TT / 8, BB), 256>>>(vt);
        softmax_t_kernel<<<BB, 256>>>();
        context_kernel<<<dim3(HH / 128, BB), 128>>>();
        dec_gru_kernel<<<dim3(BB / 64, HH / 32), 256>>>(dWhh, dbih, dbhh, s);
        pred_kernel<<<BB, 288>>>(Wfc, bfc, out, s);
    }
}